// round 17
// baseline (speedup 1.0000x reference)
#include <cuda_runtime.h>

#define NS      4
#define NA      8192
#define NC      8
#define THR2    1.21f
#define GRID    32
#define GRIDXY  (GRID * GRID)
#define CELLS   (GRID * GRID * GRID)     // 32768
#define ORIGIN  (-17.632f)
#define INV_H   (1.0f / 1.102f)          // h = 1.102 > 1.1 clash radius
#define NBLK    128                      // <= #SMs -> co-resident, gsync valid

// Device-global scratch. Replay invariants: g_counts, g_npc, g_cellCounts,
// g_sync* are zero on entry (zero-init at load; consumers re-zero after use).
__device__ int g_counts[NS * NC * NC];
__device__ int g_npc[NC];
__device__ int g_sync0, g_sync1, g_sync2, g_sync3, g_sync4;
__device__ int g_partial[NS * 32];       // per-chunk scan partials
__device__ int g_chain[NA];
__device__ __align__(16) int    g_cellCounts[NS][CELLS];
__device__ __align__(16) int    g_cellStarts[NS][CELLS + 4];
__device__ __align__(16) float4 g_pk[NS][NA];   // (x,y,z,q) cell-sorted
__device__ int    g_meta[NS][NA];               // chain of sorted atom

__device__ __forceinline__ int cellco(float v) {
    int c = __float2int_rd((v - ORIGIN) * INV_H);
    return min(GRID - 1, max(0, c));
}

// Grid barrier: valid because all NBLK blocks are co-resident (NBLK <= SMs).
// nanosleep poll (measured cheaper than pure spin). prev (if non-null) is
// reset by the LAST arriver — every block already passed prev's poll.
__device__ __forceinline__ void gsync(int* ctr, int* prev) {
    __threadfence();
    __syncthreads();
    if (threadIdx.x == 0) {
        int r = atomicAdd(ctr, 1);
        if (prev && r == NBLK - 1) *prev = 0;
        while (*(volatile int*)ctr < NBLK) __nanosleep(32);
    }
    __syncthreads();
    __threadfence();
}

// ---------------------------------------------------------------------------
// ONE persistent kernel: hist -> scan -> scatter -> search -> finalize.
// Build phases = validated R13 build. Search = validated R11 5-segment
// forward half-stencil (one thread walks all 5 segments of one sorted atom);
// identical fp32 predicate association. Shared counts are kept PER SAMPLE
// (scnt[4][64]) so the block-strided warp->atom map cannot mix samples.
// Finalize runs in block 0 after the last barrier.
// out layout: [ has (256 floats) | details (512 floats, (tot, rel)) ]
__global__ __launch_bounds__(256) void clash_kernel(
    const float* __restrict__ coord,
    const int*   __restrict__ asym,
    const int*   __restrict__ a2t,
    float*       __restrict__ out)
{
    __shared__ float s_c[768];
    __shared__ int s_w[8];
    __shared__ int s_off;
    __shared__ int scnt[NS][NC * NC];    // per-sample buckets (1 KB)

    int tid = threadIdx.x;
    int t   = blockIdx.x * 256 + tid;    // 0 .. NS*NA-1 (exactly grid size)
    int s   = t >> 13;
    int a   = t & (NA - 1);

    // ---- P1: coalesced coord stage, histogram (rank = atomic return) ------
    {
        const float* cb = coord + (size_t)blockIdx.x * 768;
        s_c[tid]       = cb[tid];
        s_c[tid + 256] = cb[tid + 256];
        s_c[tid + 512] = cb[tid + 512];
    }
    __syncthreads();
    float x = s_c[3 * tid], y = s_c[3 * tid + 1], z = s_c[3 * tid + 2];
    float q = fmaf(x, x, fmaf(y, y, z * z));
    int cell = cellco(x) + GRID * cellco(y) + GRIDXY * cellco(z);
    int rank = atomicAdd(&g_cellCounts[s][cell], 1);
    if (t < NA) {
        int ch = asym[a2t[t]];
        g_chain[t] = ch;
        atomicAdd(&g_npc[ch], 1);
    }

    gsync(&g_sync0, 0);

    // ---- P2a: local scan of this block's 1024-cell chunk ------------------
    int sb = blockIdx.x >> 5;
    int ch = blockIdx.x & 31;
    int base = ch * 1024 + tid * 4;
    int4 v = *(const int4*)(g_cellCounts[sb] + base);
    int sum = v.x + v.y + v.z + v.w;

    int lane = tid & 31, wid = tid >> 5;
    int inc = sum;
#pragma unroll
    for (int d = 1; d < 32; d <<= 1) {
        int u = __shfl_up_sync(0xFFFFFFFF, inc, d);
        if (lane >= d) inc += u;
    }
    if (lane == 31) s_w[wid] = inc;
    __syncthreads();
    if (tid < 8) {
        int wv = s_w[tid];
        int wi = wv;
#pragma unroll
        for (int d = 1; d < 8; d <<= 1) {
            int u = __shfl_up_sync(0xFF, wi, d);
            if (tid >= d) wi += u;
        }
        s_w[tid] = wi - wv;
        if (tid == 7) g_partial[sb * 32 + ch] = wi;
    }
    __syncthreads();
    int run = s_w[wid] + (inc - sum);
    *(int4*)(g_cellCounts[sb] + base) = make_int4(0, 0, 0, 0);  // invariant

    gsync(&g_sync1, &g_sync0);

    // ---- P2b: add cross-chunk offset, store starts -------------------------
    if (tid < 32) {
        int pv = (tid < ch) ? g_partial[sb * 32 + tid] : 0;
#pragma unroll
        for (int d = 16; d > 0; d >>= 1)
            pv += __shfl_down_sync(0xFFFFFFFF, pv, d);
        if (tid == 0) s_off = pv;
    }
    __syncthreads();
    int off = s_off;
    int4 o;
    o.x = run + off;
    o.y = o.x + v.x;
    o.z = o.y + v.y;
    o.w = o.z + v.z;
    *(int4*)(g_cellStarts[sb] + base) = o;
    if (ch == 31 && tid == 255) g_cellStarts[sb][CELLS] = NA;

    gsync(&g_sync2, &g_sync1);

    // ---- P3: scatter from registers ----------------------------------------
    int pos = g_cellStarts[s][cell] + rank;
    g_pk[s][pos]   = make_float4(x, y, z, q);
    g_meta[s][pos] = g_chain[a];

    if (tid < NC * NC) {                 // zero all 4 sample bucket sets
#pragma unroll
        for (int ss = 0; ss < NS; ++ss) scnt[ss][tid] = 0;
    }

    gsync(&g_sync3, &g_sync2);

    // ---- P4: search — one thread per sorted atom, all 5 forward segments.
    // Warp chunk map chunk = blockIdx.x + NBLK*wid balances dense/sparse
    // cells across blocks; a warp's 32 atoms are contiguous (coalesced).
    {
        int chunk = blockIdx.x + NBLK * wid;     // 0..1023
        int ts = chunk * 32 + lane;              // global sorted index
        int ss = ts >> 13;
        int k  = ts & (NA - 1);

        float4 p  = g_pk[ss][k];
        int    ci = g_meta[ss][k];

        float m2x = -2.0f * p.x, m2y = -2.0f * p.y, m2z = -2.0f * p.z;
        float K   = p.w - THR2;

        int cx = cellco(p.x), cy = cellco(p.y), cz = cellco(p.z);
        int x0 = max(cx - 1, 0), x1 = min(cx + 1, GRID - 1);

        const int*    st = g_cellStarts[ss];
        const float4* pk = g_pk[ss];
        const int*    mt = g_meta[ss];
        int* buck = &scnt[ss][ci * NC];

        int lo[5], hi[5];                // independent range loads -> MLP
#pragma unroll
        for (int seg = 0; seg < 5; ++seg) {
            lo[seg] = 0; hi[seg] = 0;
            if (seg < 3) {
                int zz = cz + 1, yy = cy - 1 + seg;
                if (zz < GRID && yy >= 0 && yy < GRID) {
                    int row = GRID * yy + GRIDXY * zz;
                    lo[seg] = st[row + x0];
                    hi[seg] = st[row + x1 + 1];
                }
            } else if (seg == 3) {
                int yy = cy + 1;
                if (yy < GRID) {
                    int row = GRID * yy + GRIDXY * cz;
                    lo[seg] = st[row + x0];
                    hi[seg] = st[row + x1 + 1];
                }
            } else {
                int row = GRID * cy + GRIDXY * cz;
                lo[seg] = k + 1;                 // own-cell tail + fwd-x cell
                hi[seg] = st[row + x1 + 1];
            }
        }

#pragma unroll
        for (int seg = 0; seg < 5; ++seg) {
            int j = lo[seg];
            int h = hi[seg];
            for (; j + 1 < h; j += 2) {
                float4 a0 = pk[j];
                float4 a1 = pk[j + 1];
                int m0 = mt[j];
                int m1 = mt[j + 1];
                float d0 = fmaf(m2z, a0.z, fmaf(m2y, a0.y, fmaf(m2x, a0.x, a0.w))) + K;
                float d1 = fmaf(m2z, a1.z, fmaf(m2y, a1.y, fmaf(m2x, a1.x, a1.w))) + K;
                if (d0 < 0.0f && m0 != ci) atomicAdd(&buck[m0], 1);
                if (d1 < 0.0f && m1 != ci) atomicAdd(&buck[m1], 1);
            }
            if (j < h) {
                float4 a0 = pk[j];
                int m0 = mt[j];
                float d0 = fmaf(m2z, a0.z, fmaf(m2y, a0.y, fmaf(m2x, a0.x, a0.w))) + K;
                if (d0 < 0.0f && m0 != ci) atomicAdd(&buck[m0], 1);
            }
        }
    }

    __syncthreads();
    if (tid < NC * NC) {                 // flush per-sample buckets
#pragma unroll
        for (int ss = 0; ss < NS; ++ss) {
            int vv = scnt[ss][tid];
            if (vv) atomicAdd(&g_counts[ss * NC * NC + tid], vv);
        }
    }

    gsync(&g_sync4, &g_sync3);

    // ---- P5: finalize in block 0 -------------------------------------------
    if (blockIdx.x == 0) {
        int fs = tid >> 6;
        int r  = tid & 63;
        int aa = r >> 3;
        int bb = r & 7;

        int tot_i = 0;
        if (aa != bb)
            tot_i = __ldcg(&g_counts[fs * NC * NC + aa * NC + bb]) +
                    __ldcg(&g_counts[fs * NC * NC + bb * NC + aa]);
        float tot = (float)tot_i;
        float mn  = (float)min(__ldcg(&g_npc[aa]), __ldcg(&g_npc[bb]));
        float rel = tot / mn;
        bool  has = (tot > 100.0f) || (rel > 0.5f);

        out[tid]                        = has ? 1.0f : 0.0f;
        out[NS * NC * NC + 2 * tid]     = tot;
        out[NS * NC * NC + 2 * tid + 1] = rel;

        __syncthreads();                 // all reads done
        g_counts[tid] = 0;               // reset replay invariants
        if (tid < NC) g_npc[tid] = 0;
        if (tid == 0) g_sync4 = 0;
    }
}

// ---------------------------------------------------------------------------
extern "C" void kernel_launch(void* const* d_in, const int* in_sizes, int n_in,
                              void* d_out, int out_size) {
    const float* coord = (const float*)d_in[0];   // [S, N, 3] f32
    const int*   asym  = (const int*)  d_in[1];   // [N_TOKENS] i32
    const int*   a2t   = (const int*)  d_in[2];   // [N] i32
    float*       out   = (float*)d_out;

    clash_kernel<<<NBLK, 256>>>(coord, asym, a2t, out);
}